// round 11
// baseline (speedup 1.0000x reference)
#include <cuda_runtime.h>
#include <cuda_bf16.h>
#include <cuda_fp16.h>
#include <mma.h>
#include <math.h>
#include <cstdint>

using namespace nvcuda;

#define NHI 4096
#define NLO 262144
#define NT  (NHI + NLO)      /* 266240 = 260 * 1024 */
#define EHI 65536
#define ELO 524288
#define ET  (EHI + ELO)
#define DIM 128
#define NHEAD 4
#define HDIM 32
#define SCALE 0.17677669529663687f   /* 1/sqrt(32) */
#define NBLK 260             /* scan blocks */

// ---------------- scratch (device globals; no allocation allowed) ----------------
__device__ float g_q[(size_t)NT * DIM];
__device__ __half g_kvh[(size_t)NT * 256];   // k at +0, v at +128 (fp16)
__device__ float g_h[(size_t)NT * DIM];      // skip -> +agg+LN+relu in place
__device__ int g_dcnt[NT];
__device__ int g_rowptr[NT + 1];
__device__ int g_cursor[NT];
__device__ int g_col[ET];
__device__ int g_bsum[NBLK];
__device__ int g_bex[NBLK];
// W^T bf16 hi/lo images: [matrix 0..3][n 0..127][k 0..127]
__device__ __align__(16) __nv_bfloat16 g_wt_hi[4 * 128 * 128];
__device__ __align__(16) __nv_bfloat16 g_wt_lo[4 * 128 * 128];
// bias rows: [matrix][128]
__device__ __align__(16) float g_brow[4 * 128];

// ---------------- helpers ----------------
__device__ __forceinline__ float warp_sum(float v) {
    #pragma unroll
    for (int o = 16; o; o >>= 1) v += __shfl_xor_sync(0xffffffffu, v, o);
    return v;
}
__device__ __forceinline__ uint32_t smem_u32(const void* p) {
    uint32_t a;
    asm("{ .reg .u64 t; cvta.to.shared.u64 t, %1; cvt.u32.u64 %0, t; }"
        : "=r"(a) : "l"(p));
    return a;
}
__device__ __forceinline__ void cp_async16(uint32_t dst, const void* src) {
    asm volatile("cp.async.cg.shared.global [%0], [%1], 16;" :: "r"(dst), "l"(src));
}
__device__ __forceinline__ float4 hf8_to_f4(uint2 raw) {
    __half2 h0 = ((const __half2*)&raw)[0];
    __half2 h1 = ((const __half2*)&raw)[1];
    float2 f0 = __half22float2(h0);
    float2 f1 = __half22float2(h1);
    return make_float4(f0.x, f0.y, f1.x, f1.y);
}

// ---------------- K0a: prep weights -> W^T bf16 hi/lo ----------------
__global__ void prep_w(const float* __restrict__ Wq, const float* __restrict__ Wk,
                       const float* __restrict__ Wv, const float* __restrict__ Ws)
{
    int idx = blockIdx.x * 256 + threadIdx.x;  // 0..65535
    int m = idx >> 14;       // matrix 0..3
    int n = (idx >> 7) & 127;
    int k = idx & 127;
    const float* W = (m == 0) ? Wq : (m == 1) ? Wk : (m == 2) ? Wv : Ws;
    float w = W[k * 128 + n];
    __nv_bfloat16 hi = __float2bfloat16(w);
    __nv_bfloat16 lo = __float2bfloat16(w - __bfloat162float(hi));
    g_wt_hi[idx] = hi;
    g_wt_lo[idx] = lo;
}

// ---------------- K0b: prep bias rows ----------------
__global__ void prep_b(const float* __restrict__ bq, const float* __restrict__ bk,
                       const float* __restrict__ bv, const float* __restrict__ bs)
{
    int idx = blockIdx.x * 256 + threadIdx.x;  // 0..511
    int m = idx >> 7;
    int n = idx & 127;
    const float* B = (m == 0) ? bq : (m == 1) ? bk : (m == 2) ? bv : bs;
    g_brow[idx] = B[n];
}

// ---------------- K1: fused QKV+skip GEMM via HMMA (bf16x3, M=64 tiles, 2 CTA/SM) ----------------
// SMEM (bf16 elems): A_hi[64*136], A_lo[64*136], B_hi[128*136], B_lo[128*136], bias 16x128 f32
#define TILE_M 64
#define LDA 136
#define A_ELEMS (TILE_M * LDA)          /* 8704 */
#define SM_ALO  A_ELEMS
#define SM_BH   (2 * A_ELEMS)           /* 17408 */
#define SM_BL   (SM_BH + 128 * LDA)     /* 34816 */
#define SM_BIAS_ELEMS (SM_BL + 128 * LDA)   /* 52224 bf16 elems */
#define SM_BYTES (SM_BIAS_ELEMS * 2 + 16 * 128 * 4)  /* 104448 + 8192 = 112640 */
#define LDS_STAGE 132                   /* f32 staging stride (64*132*4 = 33792 <= B area) */

__global__ void __launch_bounds__(256, 2)
gemm_hmma(const float* __restrict__ xh, const float* __restrict__ xl)
{
    extern __shared__ __nv_bfloat16 sm[];
    float* bias_s = (float*)(sm + SM_BIAS_ELEMS);   // 16 x 128 fp32
    const uint32_t sbase = smem_u32(sm);
    const int t = threadIdx.x;
    const int wid = t >> 5;
    const int wm = wid & 1;        // warp row group: 32 rows each (64-row tile)
    const int wn = wid >> 1;       // warp col group: 32 cols each (128 cols)

    // ---- load + split-convert A tile (64 rows x 128 k) ----
    const int row0 = blockIdx.x * TILE_M;
    const float* X = (row0 < NHI) ? (xh + (size_t)row0 * DIM)
                                  : (xl + (size_t)(row0 - NHI) * DIM);
    #pragma unroll
    for (int j = 0; j < 8; j++) {
        int v = t + 256 * j;            // float4 index 0..2047
        int r = v >> 5;                 // row 0..63
        int k0 = (v & 31) * 4;          // k 0..124
        float4 x = ((const float4*)X)[v];
        float xs[4] = {x.x, x.y, x.z, x.w};
        unsigned short h[4], l[4];
        #pragma unroll
        for (int i = 0; i < 4; i++) {
            __nv_bfloat16 bh = __float2bfloat16(xs[i]);
            __nv_bfloat16 bl = __float2bfloat16(xs[i] - __bfloat162float(bh));
            h[i] = *(unsigned short*)&bh;
            l[i] = *(unsigned short*)&bl;
        }
        uint2 hv = make_uint2((uint32_t)h[0] | ((uint32_t)h[1] << 16),
                              (uint32_t)h[2] | ((uint32_t)h[3] << 16));
        uint2 lv = make_uint2((uint32_t)l[0] | ((uint32_t)l[1] << 16),
                              (uint32_t)l[2] | ((uint32_t)l[3] << 16));
        *(uint2*)(sm + r * LDA + k0)          = hv;
        *(uint2*)(sm + SM_ALO + r * LDA + k0) = lv;
    }

    #pragma unroll
    for (int m = 0; m < 4; m++) {
        // load B[m] (single buffer; co-resident CTA hides the wait)
        {
            const uint4* ghi = (const uint4*)(g_wt_hi + m * 128 * 128);
            const uint4* glo = (const uint4*)(g_wt_lo + m * 128 * 128);
            uint32_t bhi = sbase + SM_BH * 2;
            uint32_t blo = sbase + SM_BL * 2;
            #pragma unroll
            for (int j = 0; j < 8; j++) {
                int idx = t + 256 * j;      // 0..2047 (16B chunks)
                int n = idx >> 4;
                int c = idx & 15;
                uint32_t off = (uint32_t)(n * LDA + c * 8) * 2;
                cp_async16(bhi + off, ghi + idx);
                cp_async16(blo + off, glo + idx);
            }
            asm volatile("cp.async.commit_group;");
        }
        // stage bias rows (16 identical rows) into smem for acc init
        {
            float b = g_brow[m * 128 + (t & 127)];
            #pragma unroll
            for (int r = t >> 7; r < 16; r += 2)
                bias_s[r * 128 + (t & 127)] = b;
        }
        asm volatile("cp.async.wait_group 0;");
        __syncthreads();   // B[m]+bias ready

        const __nv_bfloat16* Bhi = sm + SM_BH;
        const __nv_bfloat16* Blo = sm + SM_BL;

        wmma::fragment<wmma::accumulator, 16, 16, 16, float> acc[2][2];
        #pragma unroll
        for (int i = 0; i < 2; i++)
            #pragma unroll
            for (int j = 0; j < 2; j++)
                wmma::load_matrix_sync(acc[i][j],
                    bias_s + wn * 32 + j * 16, 128, wmma::mem_row_major);

        #pragma unroll
        for (int ks = 0; ks < 8; ks++) {
            wmma::fragment<wmma::matrix_a, 16, 16, 16, __nv_bfloat16, wmma::row_major> ah[2], al[2];
            wmma::fragment<wmma::matrix_b, 16, 16, 16, __nv_bfloat16, wmma::col_major> bh[2], bl[2];
            #pragma unroll
            for (int i = 0; i < 2; i++) {
                int r = wm * 32 + i * 16;
                wmma::load_matrix_sync(ah[i], sm + r * LDA + ks * 16, LDA);
                wmma::load_matrix_sync(al[i], sm + SM_ALO + r * LDA + ks * 16, LDA);
            }
            #pragma unroll
            for (int j = 0; j < 2; j++) {
                int n = wn * 32 + j * 16;
                wmma::load_matrix_sync(bh[j], Bhi + n * LDA + ks * 16, LDA);
                wmma::load_matrix_sync(bl[j], Blo + n * LDA + ks * 16, LDA);
            }
            #pragma unroll
            for (int i = 0; i < 2; i++)
                #pragma unroll
                for (int j = 0; j < 2; j++) {
                    wmma::mma_sync(acc[i][j], ah[i], bh[j], acc[i][j]);
                    wmma::mma_sync(acc[i][j], al[i], bh[j], acc[i][j]);
                    wmma::mma_sync(acc[i][j], ah[i], bl[j], acc[i][j]);
                }
        }

        if (m == 0 || m == 3) {
            // q / h: direct f32 store
            float* O = ((m == 0) ? g_q : g_h) + (size_t)row0 * DIM;
            #pragma unroll
            for (int i = 0; i < 2; i++)
                #pragma unroll
                for (int j = 0; j < 2; j++)
                    wmma::store_matrix_sync(
                        O + (size_t)(wm * 32 + i * 16) * DIM + wn * 32 + j * 16,
                        acc[i][j], DIM, wmma::mem_row_major);
            __syncthreads();   // phase barrier before next B load overwrites buffer
        } else {
            // k / v: stage f32 in the B buffer (done being read), convert to fp16, store
            __syncthreads();   // all warps done reading B[m]
            float* stage = (float*)(sm + SM_BH);
            #pragma unroll
            for (int i = 0; i < 2; i++)
                #pragma unroll
                for (int j = 0; j < 2; j++)
                    wmma::store_matrix_sync(
                        stage + (wm * 32 + i * 16) * LDS_STAGE + wn * 32 + j * 16,
                        acc[i][j], LDS_STAGE, wmma::mem_row_major);
            __syncthreads();
            __half* dst = g_kvh + (size_t)row0 * 256 + ((m == 1) ? 0 : 128);
            #pragma unroll
            for (int j = 0; j < 8; j++) {
                int v = t + 256 * j;        // 0..2047
                int r = v >> 5;
                int c = (v & 31) * 4;
                float4 x = *(const float4*)(stage + r * LDS_STAGE + c);
                __half2 p0 = __floats2half2_rn(x.x, x.y);
                __half2 p1 = __floats2half2_rn(x.z, x.w);
                uint2 o = make_uint2(*(uint32_t*)&p0, *(uint32_t*)&p1);
                *(uint2*)(dst + (size_t)r * 256 + c) = o;
            }
            __syncthreads();   // staging free before next B load
        }
    }
}

// ---------------- CSR build ----------------
__global__ void edge_hist(const int* __restrict__ eih, const int* __restrict__ eil)
{
    int e = blockIdx.x * 256 + threadIdx.x;
    if (e >= ET) return;
    int dst = (e < EHI) ? eih[EHI + e] : (eil[ELO + (e - EHI)] + NHI);
    atomicAdd(&g_dcnt[dst], 1);
}

__global__ void scan_local()
{
    __shared__ int sh[1024];
    const int t = threadIdx.x;
    const int i = blockIdx.x * 1024 + t;
    int v = g_dcnt[i];
    sh[t] = v;
    __syncthreads();
    #pragma unroll
    for (int off = 1; off < 1024; off <<= 1) {
        int u = (t >= off) ? sh[t - off] : 0;
        __syncthreads();
        sh[t] += u;
        __syncthreads();
    }
    g_rowptr[i] = sh[t] - v;            // local exclusive
    if (t == 1023) g_bsum[blockIdx.x] = sh[t];
}

__global__ void scan_bsum()
{
    __shared__ int sh[512];
    const int t = threadIdx.x;          // 512 threads
    int v = (t < NBLK) ? g_bsum[t] : 0;
    sh[t] = v;
    __syncthreads();
    #pragma unroll
    for (int off = 1; off < 512; off <<= 1) {
        int u = (t >= off) ? sh[t - off] : 0;
        __syncthreads();
        sh[t] += u;
        __syncthreads();
    }
    if (t < NBLK) g_bex[t] = sh[t] - v; // exclusive block base
    if (t == 511) g_rowptr[NT] = sh[511];
}

__global__ void scan_add()
{
    const int i = blockIdx.x * 1024 + threadIdx.x;
    int r = g_rowptr[i] + g_bex[blockIdx.x];
    g_rowptr[i] = r;
    g_cursor[i] = r;
}

__global__ void edge_scatter(const int* __restrict__ eih, const int* __restrict__ eil)
{
    int e = blockIdx.x * 256 + threadIdx.x;
    if (e >= ET) return;
    int src, dst;
    if (e < EHI) { src = eih[e];             dst = eih[EHI + e]; }
    else         { src = eil[e - EHI] + NHI; dst = eil[ELO + (e - EHI)] + NHI; }
    int pos = atomicAdd(&g_cursor[dst], 1);
    g_col[pos] = src;
}

// ---------------- K2: one-pass attention (online softmax) + fused LN/ReLU ----------------
// lane owns 4 contiguous columns [lane*4, lane*4+4); head = lane>>3.
__global__ void __launch_bounds__(256)
attn_ln(const float* __restrict__ lnw, const float* __restrict__ lnb)
{
    int node = blockIdx.x * 8 + threadIdx.y;
    int lane = threadIdx.x;
    int s = g_rowptr[node];
    int e1 = g_rowptr[node + 1];

    float* hr = g_h + (size_t)node * DIM;
    float4 val = ((float4*)hr)[lane];   // skip term

    if (s < e1) {
        float4 qv = ((const float4*)(g_q + (size_t)node * DIM))[lane];

        float m = -INFINITY, d = 0.f;
        float4 acc = make_float4(0.f, 0.f, 0.f, 0.f);

        // 1-deep software pipeline on the kv gather (512B contiguous per edge)
        const uint2* kvp = (const uint2*)(g_kvh + (size_t)g_col[s] * 256);
        uint2 kraw = kvp[lane];
        uint2 vraw = kvp[lane + 32];
        for (int i = s; i < e1; i++) {
            float4 kc = hf8_to_f4(kraw);
            float4 vc = hf8_to_f4(vraw);
            if (i + 1 < e1) {
                const uint2* np = (const uint2*)(g_kvh + (size_t)g_col[i + 1] * 256);
                kraw = np[lane];
                vraw = np[lane + 32];
            }
            float p = qv.x * kc.x + qv.y * kc.y + qv.z * kc.z + qv.w * kc.w;
            p += __shfl_xor_sync(0xffffffffu, p, 4);
            p += __shfl_xor_sync(0xffffffffu, p, 2);
            p += __shfl_xor_sync(0xffffffffu, p, 1);
            float sc = p * SCALE;            // this lane's head score
            float mn = fmaxf(m, sc);
            float c = __expf(m - mn);        // 0 when m was -inf
            float w = __expf(sc - mn);
            d = d * c + w;
            acc.x = acc.x * c + w * vc.x;
            acc.y = acc.y * c + w * vc.y;
            acc.z = acc.z * c + w * vc.z;
            acc.w = acc.w * c + w * vc.w;
            m = mn;
        }
        float inv = 1.0f / d;
        val.x += acc.x * inv;
        val.y += acc.y * inv;
        val.z += acc.z * inv;
        val.w += acc.w * inv;
    }

    // fused LayerNorm + ReLU (warp holds the full 128-dim row)
    float sum = warp_sum(val.x + val.y + val.z + val.w);
    float sq = warp_sum(val.x * val.x + val.y * val.y + val.z * val.z + val.w * val.w);
    float mean = sum * (1.0f / 128.0f);
    float var = sq * (1.0f / 128.0f) - mean * mean;
    float rstd = rsqrtf(var + 1e-5f);
    float4 w4 = ((const float4*)lnw)[lane];
    float4 b4 = ((const float4*)lnb)[lane];
    float4 o;
    o.x = fmaxf((val.x - mean) * rstd * w4.x + b4.x, 0.0f);
    o.y = fmaxf((val.y - mean) * rstd * w4.y + b4.y, 0.0f);
    o.z = fmaxf((val.z - mean) * rstd * w4.z + b4.z, 0.0f);
    o.w = fmaxf((val.w - mean) * rstd * w4.w + b4.w, 0.0f);
    ((float4*)hr)[lane] = o;
}

// ---------------- K3: segmented pool + high-node gating (one warp per high node) ----------------
__device__ __forceinline__ int lower_bound_batch(const int* __restrict__ batch, int key)
{
    int lo = 0, hi = NLO;
    while (lo < hi) {
        int mid = (lo + hi) >> 1;
        if (batch[mid] < key) lo = mid + 1; else hi = mid;
    }
    return lo;
}

__global__ void __launch_bounds__(256)
pool_final_high(const int* __restrict__ batch, const float* __restrict__ wlh,
                float* __restrict__ out)
{
    int g = blockIdx.x * 8 + threadIdx.y;
    int lane = threadIdx.x;
    int lb = lower_bound_batch(batch, g);
    int ub = lower_bound_batch(batch, g + 1);

    float4 s = make_float4(0.f, 0.f, 0.f, 0.f);
    for (int j = lb; j < ub; j++) {
        float4 lr = ((const float4*)(g_h + (size_t)(NHI + j) * DIM))[lane];
        s.x += lr.x; s.y += lr.y; s.z += lr.z; s.w += lr.w;
    }
    float inv = 1.0f / fmaxf((float)(ub - lb), 1.0f);
    float4 pv = make_float4(s.x * inv, s.y * inv, s.z * inv, s.w * inv);

    float4 hv = ((const float4*)(g_h + (size_t)g * DIM))[lane];
    float4 w0 = ((const float4*)wlh)[lane];
    float4 w1 = ((const float4*)(wlh + DIM))[lane];
    float dot = hv.x * w0.x + hv.y * w0.y + hv.z * w0.z + hv.w * w0.w
              + pv.x * w1.x + pv.y * w1.y + pv.z * w1.z + pv.w * w1.w;
    dot = warp_sum(dot);
    float sgm = 1.0f / (1.0f + __expf(-dot));
    float4 o;
    o.x = sgm * hv.x + (1.0f - sgm) * pv.x;
    o.y = sgm * hv.y + (1.0f - sgm) * pv.y;
    o.z = sgm * hv.z + (1.0f - sgm) * pv.z;
    o.w = sgm * hv.w + (1.0f - sgm) * pv.w;
    ((float4*)(out + (size_t)g * DIM))[lane] = o;
}

// ---------------- K4: low-node gating epilogue ----------------
__global__ void final_low(const float* __restrict__ whl, const int* __restrict__ batch,
                          float* __restrict__ out)
{
    int j = blockIdx.x * 8 + threadIdx.y;
    int lane = threadIdx.x;
    int g = batch[j];
    float4 hb = ((const float4*)(g_h + (size_t)g * DIM))[lane];
    float4 lv = ((const float4*)(g_h + (size_t)(NHI + j) * DIM))[lane];
    float4 w0 = ((const float4*)whl)[lane];
    float4 w1 = ((const float4*)(whl + DIM))[lane];
    float d = hb.x * w0.x + hb.y * w0.y + hb.z * w0.z + hb.w * w0.w
            + lv.x * w1.x + lv.y * w1.y + lv.z * w1.z + lv.w * w1.w;
    d = warp_sum(d);
    float a = 1.0f / (1.0f + __expf(-d));
    float4 o;
    o.x = a * lv.x + (1.0f - a) * hb.x;
    o.y = a * lv.y + (1.0f - a) * hb.y;
    o.z = a * lv.z + (1.0f - a) * hb.z;
    o.w = a * lv.w + (1.0f - a) * hb.w;
    ((float4*)(out + (size_t)j * DIM))[lane] = o;
}

// ---------------- launch ----------------
extern "C" void kernel_launch(void* const* d_in, const int* in_sizes, int n_in,
                              void* d_out, int out_size)
{
    const float* high_emb = (const float*)d_in[0];
    const float* low_emb  = (const float*)d_in[1];
    const float* Wq = (const float*)d_in[2];  const float* bq = (const float*)d_in[3];
    const float* Wk = (const float*)d_in[4];  const float* bk = (const float*)d_in[5];
    const float* Wv = (const float*)d_in[6];  const float* bv = (const float*)d_in[7];
    const float* Ws = (const float*)d_in[8];  const float* bs = (const float*)d_in[9];
    const float* lnw = (const float*)d_in[10];
    const float* lnb = (const float*)d_in[11];
    const float* wlh = (const float*)d_in[12];
    const float* whl = (const float*)d_in[13];
    const int* eih   = (const int*)d_in[14];
    const int* eil   = (const int*)d_in[15];
    const int* batch = (const int*)d_in[16];
    float* out = (float*)d_out;

    void* pcnt;
    cudaGetSymbolAddress(&pcnt, g_dcnt);

    cudaFuncSetAttribute(gemm_hmma, cudaFuncAttributeMaxDynamicSharedMemorySize, SM_BYTES);

    // second stream + fork/join events (graph-capture-legal pattern)
    cudaStream_t s2;
    cudaStreamCreateWithFlags(&s2, cudaStreamNonBlocking);
    cudaEvent_t evFork, evCsr, evAttn, evPool;
    cudaEventCreateWithFlags(&evFork, cudaEventDisableTiming);
    cudaEventCreateWithFlags(&evCsr,  cudaEventDisableTiming);
    cudaEventCreateWithFlags(&evAttn, cudaEventDisableTiming);
    cudaEventCreateWithFlags(&evPool, cudaEventDisableTiming);

    cudaMemsetAsync(pcnt, 0, NT * sizeof(int), 0);
    cudaEventRecord(evFork, 0);
    cudaStreamWaitEvent(s2, evFork, 0);

    // stream 0: prep + GEMM launched first (keeps gemm at the profiled slot);
    // s2's CSR chain executes concurrently regardless of launch-call order.
    prep_w<<<256, 256>>>(Wq, Wk, Wv, Ws);
    prep_b<<<2, 256>>>(bq, bk, bv, bs);
    edge_hist<<<(ET + 255) / 256, 256, 0, s2>>>(eih, eil);
    gemm_hmma<<<NT / TILE_M, 256, SM_BYTES>>>(high_emb, low_emb);

    // stream s2: rest of CSR build
    scan_local<<<NBLK, 1024, 0, s2>>>();
    scan_bsum<<<1, 512, 0, s2>>>();
    scan_add<<<NBLK, 1024, 0, s2>>>();
    edge_scatter<<<(ET + 255) / 256, 256, 0, s2>>>(eih, eil);
    cudaEventRecord(evCsr, s2);

    // join: attention needs both GEMM outputs and CSR
    cudaStreamWaitEvent(0, evCsr, 0);
    dim3 t32x8(32, 8);
    attn_ln<<<NT / 8, t32x8>>>(lnw, lnb);
    cudaEventRecord(evAttn, 0);

    // overlap the two epilogues
    cudaStreamWaitEvent(s2, evAttn, 0);
    pool_final_high<<<NHI / 8, t32x8, 0, s2>>>(batch, wlh, out);
    cudaEventRecord(evPool, s2);
    final_low<<<NLO / 8, t32x8>>>(whl, batch, out + (size_t)NHI * DIM);
    cudaStreamWaitEvent(0, evPool, 0);

    cudaEventDestroy(evFork);
    cudaEventDestroy(evCsr);
    cudaEventDestroy(evAttn);
    cudaEventDestroy(evPool);
    cudaStreamDestroy(s2);
}

// round 12
// speedup vs baseline: 1.2795x; 1.2795x over previous
#include <cuda_runtime.h>
#include <cuda_bf16.h>
#include <cuda_fp16.h>
#include <mma.h>
#include <math.h>
#include <cstdint>

using namespace nvcuda;

#define NHI 4096
#define NLO 262144
#define NT  (NHI + NLO)      /* 266240 = 260 * 1024 */
#define EHI 65536
#define ELO 524288
#define ET  (EHI + ELO)
#define DIM 128
#define NHEAD 4
#define HDIM 32
#define SCALE 0.17677669529663687f   /* 1/sqrt(32) */
#define NBLK 260             /* scan blocks */

// ---------------- scratch (device globals; no allocation allowed) ----------------
__device__ float g_q[(size_t)NT * DIM];
__device__ __half g_kvh[(size_t)NT * 256];   // k at +0, v at +128 (fp16)
__device__ float g_h[(size_t)NT * DIM];      // skip -> +agg+LN+relu in place
__device__ int g_dcnt[NT];
__device__ int g_rowptr[NT + 1];
__device__ int g_cursor[NT];
__device__ int g_col[ET];
__device__ int g_bsum[NBLK];
__device__ int g_bex[NBLK];
// W^T fp16 image: [matrix 0..3][n 0..127][k 0..127]
__device__ __align__(16) __half g_wt[4 * 128 * 128];
// bias rows: [matrix][128]
__device__ __align__(16) float g_brow[4 * 128];

// ---------------- helpers ----------------
__device__ __forceinline__ float warp_sum(float v) {
    #pragma unroll
    for (int o = 16; o; o >>= 1) v += __shfl_xor_sync(0xffffffffu, v, o);
    return v;
}
__device__ __forceinline__ uint32_t smem_u32(const void* p) {
    uint32_t a;
    asm("{ .reg .u64 t; cvta.to.shared.u64 t, %1; cvt.u32.u64 %0, t; }"
        : "=r"(a) : "l"(p));
    return a;
}
__device__ __forceinline__ void cp_async16(uint32_t dst, const void* src) {
    asm volatile("cp.async.cg.shared.global [%0], [%1], 16;" :: "r"(dst), "l"(src));
}
__device__ __forceinline__ float4 hf8_to_f4(uint2 raw) {
    __half2 h0 = ((const __half2*)&raw)[0];
    __half2 h1 = ((const __half2*)&raw)[1];
    float2 f0 = __half22float2(h0);
    float2 f1 = __half22float2(h1);
    return make_float4(f0.x, f0.y, f1.x, f1.y);
}

// ---------------- K0a: prep weights -> W^T fp16 ----------------
__global__ void prep_w(const float* __restrict__ Wq, const float* __restrict__ Wk,
                       const float* __restrict__ Wv, const float* __restrict__ Ws)
{
    int idx = blockIdx.x * 256 + threadIdx.x;  // 0..65535
    int m = idx >> 14;       // matrix 0..3
    int n = (idx >> 7) & 127;
    int k = idx & 127;
    const float* W = (m == 0) ? Wq : (m == 1) ? Wk : (m == 2) ? Wv : Ws;
    g_wt[idx] = __float2half(W[k * 128 + n]);
}

// ---------------- K0b: prep bias rows ----------------
__global__ void prep_b(const float* __restrict__ bq, const float* __restrict__ bk,
                       const float* __restrict__ bv, const float* __restrict__ bs)
{
    int idx = blockIdx.x * 256 + threadIdx.x;  // 0..511
    int m = idx >> 7;
    int n = idx & 127;
    const float* B = (m == 0) ? bq : (m == 1) ? bk : (m == 2) ? bv : bs;
    g_brow[idx] = B[n];
}

// ---------------- K1: fused QKV+skip GEMM, fp16 single-product HMMA ----------------
// SMEM (half elems): A[64*136], B[128*136], then 8KB fp32 bias tile
#define TILE_M 64
#define LDA 136
#define A_ELEMS (TILE_M * LDA)          /* 8704 */
#define SM_B    A_ELEMS                 /* B at 8704 */
#define SM_BIAS_ELEMS (SM_B + 128 * LDA)    /* 26112 half elems */
#define SM_BYTES (SM_BIAS_ELEMS * 2 + 16 * 128 * 4)  /* 52224 + 8192 = 60416 */
#define LDS_STAGE 132                   /* f32 staging stride (64*132*4 = 33792 <= B area 34816) */

__global__ void __launch_bounds__(256, 3)
gemm_hmma(const float* __restrict__ xh, const float* __restrict__ xl)
{
    extern __shared__ __half sm[];
    float* bias_s = (float*)(sm + SM_BIAS_ELEMS);   // 16 x 128 fp32
    const uint32_t sbase = smem_u32(sm);
    const int t = threadIdx.x;
    const int wid = t >> 5;
    const int wm = wid & 1;        // warp row group: 32 rows each (64-row tile)
    const int wn = wid >> 1;       // warp col group: 32 cols each (128 cols)

    // ---- load + convert A tile (64 rows x 128 k) to fp16 ----
    const int row0 = blockIdx.x * TILE_M;
    const float* X = (row0 < NHI) ? (xh + (size_t)row0 * DIM)
                                  : (xl + (size_t)(row0 - NHI) * DIM);
    #pragma unroll
    for (int j = 0; j < 8; j++) {
        int v = t + 256 * j;            // float4 index 0..2047
        int r = v >> 5;                 // row 0..63
        int k0 = (v & 31) * 4;          // k 0..124
        float4 x = ((const float4*)X)[v];
        __half2 p0 = __floats2half2_rn(x.x, x.y);
        __half2 p1 = __floats2half2_rn(x.z, x.w);
        uint2 hv = make_uint2(*(uint32_t*)&p0, *(uint32_t*)&p1);
        *(uint2*)(sm + r * LDA + k0) = hv;
    }

    #pragma unroll
    for (int m = 0; m < 4; m++) {
        // load B[m] (single buffer; co-resident CTAs hide the wait)
        {
            const uint4* gw = (const uint4*)(g_wt + m * 128 * 128);
            uint32_t bb = sbase + SM_B * 2;
            #pragma unroll
            for (int j = 0; j < 8; j++) {
                int idx = t + 256 * j;      // 0..2047 (16B chunks)
                int n = idx >> 4;
                int c = idx & 15;
                uint32_t off = (uint32_t)(n * LDA + c * 8) * 2;
                cp_async16(bb + off, gw + idx);
            }
            asm volatile("cp.async.commit_group;");
        }
        // stage bias rows (16 identical rows) into smem for acc init
        {
            float b = g_brow[m * 128 + (t & 127)];
            #pragma unroll
            for (int r = t >> 7; r < 16; r += 2)
                bias_s[r * 128 + (t & 127)] = b;
        }
        asm volatile("cp.async.wait_group 0;");
        __syncthreads();   // B[m]+bias ready

        const __half* B = sm + SM_B;

        wmma::fragment<wmma::accumulator, 16, 16, 16, float> acc[2][2];
        #pragma unroll
        for (int i = 0; i < 2; i++)
            #pragma unroll
            for (int j = 0; j < 2; j++)
                wmma::load_matrix_sync(acc[i][j],
                    bias_s + wn * 32 + j * 16, 128, wmma::mem_row_major);

        #pragma unroll
        for (int ks = 0; ks < 8; ks++) {
            wmma::fragment<wmma::matrix_a, 16, 16, 16, __half, wmma::row_major> af[2];
            wmma::fragment<wmma::matrix_b, 16, 16, 16, __half, wmma::col_major> bf[2];
            #pragma unroll
            for (int i = 0; i < 2; i++)
                wmma::load_matrix_sync(af[i], sm + (wm * 32 + i * 16) * LDA + ks * 16, LDA);
            #pragma unroll
            for (int j = 0; j < 2; j++)
                wmma::load_matrix_sync(bf[j], B + (wn * 32 + j * 16) * LDA + ks * 16, LDA);
            #pragma unroll
            for (int i = 0; i < 2; i++)
                #pragma unroll
                for (int j = 0; j < 2; j++)
                    wmma::mma_sync(acc[i][j], af[i], bf[j], acc[i][j]);
        }

        if (m == 0 || m == 3) {
            // q / h: direct f32 store
            float* O = ((m == 0) ? g_q : g_h) + (size_t)row0 * DIM;
            #pragma unroll
            for (int i = 0; i < 2; i++)
                #pragma unroll
                for (int j = 0; j < 2; j++)
                    wmma::store_matrix_sync(
                        O + (size_t)(wm * 32 + i * 16) * DIM + wn * 32 + j * 16,
                        acc[i][j], DIM, wmma::mem_row_major);
            __syncthreads();   // phase barrier before next B load overwrites buffer
        } else {
            // k / v: stage f32 in the B buffer (done being read), convert to fp16, store
            __syncthreads();   // all warps done reading B[m]
            float* stage = (float*)(sm + SM_B);
            #pragma unroll
            for (int i = 0; i < 2; i++)
                #pragma unroll
                for (int j = 0; j < 2; j++)
                    wmma::store_matrix_sync(
                        stage + (wm * 32 + i * 16) * LDS_STAGE + wn * 32 + j * 16,
                        acc[i][j], LDS_STAGE, wmma::mem_row_major);
            __syncthreads();
            __half* dst = g_kvh + (size_t)row0 * 256 + ((m == 1) ? 0 : 128);
            #pragma unroll
            for (int j = 0; j < 8; j++) {
                int v = t + 256 * j;        // 0..2047
                int r = v >> 5;
                int c = (v & 31) * 4;
                float4 x = *(const float4*)(stage + r * LDS_STAGE + c);
                __half2 p0 = __floats2half2_rn(x.x, x.y);
                __half2 p1 = __floats2half2_rn(x.z, x.w);
                uint2 o = make_uint2(*(uint32_t*)&p0, *(uint32_t*)&p1);
                *(uint2*)(dst + (size_t)r * 256 + c) = o;
            }
            __syncthreads();   // staging free before next B load
        }
    }
}

// ---------------- CSR build ----------------
__global__ void edge_hist(const int* __restrict__ eih, const int* __restrict__ eil)
{
    int e = blockIdx.x * 256 + threadIdx.x;
    if (e >= ET) return;
    int dst = (e < EHI) ? eih[EHI + e] : (eil[ELO + (e - EHI)] + NHI);
    atomicAdd(&g_dcnt[dst], 1);
}

__global__ void scan_local()
{
    __shared__ int sh[1024];
    const int t = threadIdx.x;
    const int i = blockIdx.x * 1024 + t;
    int v = g_dcnt[i];
    sh[t] = v;
    __syncthreads();
    #pragma unroll
    for (int off = 1; off < 1024; off <<= 1) {
        int u = (t >= off) ? sh[t - off] : 0;
        __syncthreads();
        sh[t] += u;
        __syncthreads();
    }
    g_rowptr[i] = sh[t] - v;            // local exclusive
    if (t == 1023) g_bsum[blockIdx.x] = sh[t];
}

__global__ void scan_bsum()
{
    __shared__ int sh[512];
    const int t = threadIdx.x;          // 512 threads
    int v = (t < NBLK) ? g_bsum[t] : 0;
    sh[t] = v;
    __syncthreads();
    #pragma unroll
    for (int off = 1; off < 512; off <<= 1) {
        int u = (t >= off) ? sh[t - off] : 0;
        __syncthreads();
        sh[t] += u;
        __syncthreads();
    }
    if (t < NBLK) g_bex[t] = sh[t] - v; // exclusive block base
    if (t == 511) g_rowptr[NT] = sh[511];
}

__global__ void scan_add()
{
    const int i = blockIdx.x * 1024 + threadIdx.x;
    int r = g_rowptr[i] + g_bex[blockIdx.x];
    g_rowptr[i] = r;
    g_cursor[i] = r;
}

__global__ void edge_scatter(const int* __restrict__ eih, const int* __restrict__ eil)
{
    int e = blockIdx.x * 256 + threadIdx.x;
    if (e >= ET) return;
    int src, dst;
    if (e < EHI) { src = eih[e];             dst = eih[EHI + e]; }
    else         { src = eil[e - EHI] + NHI; dst = eil[ELO + (e - EHI)] + NHI; }
    int pos = atomicAdd(&g_cursor[dst], 1);
    g_col[pos] = src;
}

// ---------------- K2: one-pass attention (online softmax) + fused LN/ReLU ----------------
// lane owns 4 contiguous columns [lane*4, lane*4+4); head = lane>>3.
__global__ void __launch_bounds__(256)
attn_ln(const float* __restrict__ lnw, const float* __restrict__ lnb)
{
    int node = blockIdx.x * 8 + threadIdx.y;
    int lane = threadIdx.x;
    int s = g_rowptr[node];
    int e1 = g_rowptr[node + 1];

    float* hr = g_h + (size_t)node * DIM;
    float4 val = ((float4*)hr)[lane];   // skip term

    if (s < e1) {
        float4 qv = ((const float4*)(g_q + (size_t)node * DIM))[lane];

        float m = -INFINITY, d = 0.f;
        float4 acc = make_float4(0.f, 0.f, 0.f, 0.f);

        // 1-deep software pipeline on the kv gather (512B contiguous per edge)
        const uint2* kvp = (const uint2*)(g_kvh + (size_t)g_col[s] * 256);
        uint2 kraw = kvp[lane];
        uint2 vraw = kvp[lane + 32];
        for (int i = s; i < e1; i++) {
            float4 kc = hf8_to_f4(kraw);
            float4 vc = hf8_to_f4(vraw);
            if (i + 1 < e1) {
                const uint2* np = (const uint2*)(g_kvh + (size_t)g_col[i + 1] * 256);
                kraw = np[lane];
                vraw = np[lane + 32];
            }
            float p = qv.x * kc.x + qv.y * kc.y + qv.z * kc.z + qv.w * kc.w;
            p += __shfl_xor_sync(0xffffffffu, p, 4);
            p += __shfl_xor_sync(0xffffffffu, p, 2);
            p += __shfl_xor_sync(0xffffffffu, p, 1);
            float sc = p * SCALE;            // this lane's head score
            float mn = fmaxf(m, sc);
            float c = __expf(m - mn);        // 0 when m was -inf
            float w = __expf(sc - mn);
            d = d * c + w;
            acc.x = acc.x * c + w * vc.x;
            acc.y = acc.y * c + w * vc.y;
            acc.z = acc.z * c + w * vc.z;
            acc.w = acc.w * c + w * vc.w;
            m = mn;
        }
        float inv = 1.0f / d;
        val.x += acc.x * inv;
        val.y += acc.y * inv;
        val.z += acc.z * inv;
        val.w += acc.w * inv;
    }

    // fused LayerNorm + ReLU (warp holds the full 128-dim row)
    float sum = warp_sum(val.x + val.y + val.z + val.w);
    float sq = warp_sum(val.x * val.x + val.y * val.y + val.z * val.z + val.w * val.w);
    float mean = sum * (1.0f / 128.0f);
    float var = sq * (1.0f / 128.0f) - mean * mean;
    float rstd = rsqrtf(var + 1e-5f);
    float4 w4 = ((const float4*)lnw)[lane];
    float4 b4 = ((const float4*)lnb)[lane];
    float4 o;
    o.x = fmaxf((val.x - mean) * rstd * w4.x + b4.x, 0.0f);
    o.y = fmaxf((val.y - mean) * rstd * w4.y + b4.y, 0.0f);
    o.z = fmaxf((val.z - mean) * rstd * w4.z + b4.z, 0.0f);
    o.w = fmaxf((val.w - mean) * rstd * w4.w + b4.w, 0.0f);
    ((float4*)hr)[lane] = o;
}

// ---------------- K3: segmented pool + high-node gating (one warp per high node) ----------------
__device__ __forceinline__ int lower_bound_batch(const int* __restrict__ batch, int key)
{
    int lo = 0, hi = NLO;
    while (lo < hi) {
        int mid = (lo + hi) >> 1;
        if (batch[mid] < key) lo = mid + 1; else hi = mid;
    }
    return lo;
}

__global__ void __launch_bounds__(256)
pool_final_high(const int* __restrict__ batch, const float* __restrict__ wlh,
                float* __restrict__ out)
{
    int g = blockIdx.x * 8 + threadIdx.y;
    int lane = threadIdx.x;
    int lb = lower_bound_batch(batch, g);
    int ub = lower_bound_batch(batch, g + 1);

    float4 s = make_float4(0.f, 0.f, 0.f, 0.f);
    for (int j = lb; j < ub; j++) {
        float4 lr = ((const float4*)(g_h + (size_t)(NHI + j) * DIM))[lane];
        s.x += lr.x; s.y += lr.y; s.z += lr.z; s.w += lr.w;
    }
    float inv = 1.0f / fmaxf((float)(ub - lb), 1.0f);
    float4 pv = make_float4(s.x * inv, s.y * inv, s.z * inv, s.w * inv);

    float4 hv = ((const float4*)(g_h + (size_t)g * DIM))[lane];
    float4 w0 = ((const float4*)wlh)[lane];
    float4 w1 = ((const float4*)(wlh + DIM))[lane];
    float dot = hv.x * w0.x + hv.y * w0.y + hv.z * w0.z + hv.w * w0.w
              + pv.x * w1.x + pv.y * w1.y + pv.z * w1.z + pv.w * w1.w;
    dot = warp_sum(dot);
    float sgm = 1.0f / (1.0f + __expf(-dot));
    float4 o;
    o.x = sgm * hv.x + (1.0f - sgm) * pv.x;
    o.y = sgm * hv.y + (1.0f - sgm) * pv.y;
    o.z = sgm * hv.z + (1.0f - sgm) * pv.z;
    o.w = sgm * hv.w + (1.0f - sgm) * pv.w;
    ((float4*)(out + (size_t)g * DIM))[lane] = o;
}

// ---------------- K4: low-node gating epilogue ----------------
__global__ void final_low(const float* __restrict__ whl, const int* __restrict__ batch,
                          float* __restrict__ out)
{
    int j = blockIdx.x * 8 + threadIdx.y;
    int lane = threadIdx.x;
    int g = batch[j];
    float4 hb = ((const float4*)(g_h + (size_t)g * DIM))[lane];
    float4 lv = ((const float4*)(g_h + (size_t)(NHI + j) * DIM))[lane];
    float4 w0 = ((const float4*)whl)[lane];
    float4 w1 = ((const float4*)(whl + DIM))[lane];
    float d = hb.x * w0.x + hb.y * w0.y + hb.z * w0.z + hb.w * w0.w
            + lv.x * w1.x + lv.y * w1.y + lv.z * w1.z + lv.w * w1.w;
    d = warp_sum(d);
    float a = 1.0f / (1.0f + __expf(-d));
    float4 o;
    o.x = a * lv.x + (1.0f - a) * hb.x;
    o.y = a * lv.y + (1.0f - a) * hb.y;
    o.z = a * lv.z + (1.0f - a) * hb.z;
    o.w = a * lv.w + (1.0f - a) * hb.w;
    ((float4*)(out + (size_t)j * DIM))[lane] = o;
}

// ---------------- launch ----------------
extern "C" void kernel_launch(void* const* d_in, const int* in_sizes, int n_in,
                              void* d_out, int out_size)
{
    const float* high_emb = (const float*)d_in[0];
    const float* low_emb  = (const float*)d_in[1];
    const float* Wq = (const float*)d_in[2];  const float* bq = (const float*)d_in[3];
    const float* Wk = (const float*)d_in[4];  const float* bk = (const float*)d_in[5];
    const float* Wv = (const float*)d_in[6];  const float* bv = (const float*)d_in[7];
    const float* Ws = (const float*)d_in[8];  const float* bs = (const float*)d_in[9];
    const float* lnw = (const float*)d_in[10];
    const float* lnb = (const float*)d_in[11];
    const float* wlh = (const float*)d_in[12];
    const float* whl = (const float*)d_in[13];
    const int* eih   = (const int*)d_in[14];
    const int* eil   = (const int*)d_in[15];
    const int* batch = (const int*)d_in[16];
    float* out = (float*)d_out;

    void* pcnt;
    cudaGetSymbolAddress(&pcnt, g_dcnt);

    cudaFuncSetAttribute(gemm_hmma, cudaFuncAttributeMaxDynamicSharedMemorySize, SM_BYTES);

    // second stream + fork/join events (graph-capture-legal pattern)
    cudaStream_t s2;
    cudaStreamCreateWithFlags(&s2, cudaStreamNonBlocking);
    cudaEvent_t evFork, evCsr, evAttn, evPool;
    cudaEventCreateWithFlags(&evFork, cudaEventDisableTiming);
    cudaEventCreateWithFlags(&evCsr,  cudaEventDisableTiming);
    cudaEventCreateWithFlags(&evAttn, cudaEventDisableTiming);
    cudaEventCreateWithFlags(&evPool, cudaEventDisableTiming);

    cudaMemsetAsync(pcnt, 0, NT * sizeof(int), 0);
    cudaEventRecord(evFork, 0);
    cudaStreamWaitEvent(s2, evFork, 0);

    // stream 0: prep + GEMM (profiled slot); s2: CSR chain concurrently
    prep_w<<<256, 256>>>(Wq, Wk, Wv, Ws);
    prep_b<<<2, 256>>>(bq, bk, bv, bs);
    edge_hist<<<(ET + 255) / 256, 256, 0, s2>>>(eih, eil);
    gemm_hmma<<<NT / TILE_M, 256, SM_BYTES>>>(high_emb, low_emb);

    scan_local<<<NBLK, 1024, 0, s2>>>();
    scan_bsum<<<1, 512, 0, s2>>>();
    scan_add<<<NBLK, 1024, 0, s2>>>();
    edge_scatter<<<(ET + 255) / 256, 256, 0, s2>>>(eih, eil);
    cudaEventRecord(evCsr, s2);

    // join: attention needs both GEMM outputs and CSR
    cudaStreamWaitEvent(0, evCsr, 0);
    dim3 t32x8(32, 8);
    attn_ln<<<NT / 8, t32x8>>>(lnw, lnb);
    cudaEventRecord(evAttn, 0);

    // overlap the two epilogues
    cudaStreamWaitEvent(s2, evAttn, 0);
    pool_final_high<<<NHI / 8, t32x8, 0, s2>>>(batch, wlh, out);
    cudaEventRecord(evPool, s2);
    final_low<<<NLO / 8, t32x8>>>(whl, batch, out + (size_t)NHI * DIM);
    cudaStreamWaitEvent(0, evPool, 0);

    cudaEventDestroy(evFork);
    cudaEventDestroy(evCsr);
    cudaEventDestroy(evAttn);
    cudaEventDestroy(evPool);
    cudaStreamDestroy(s2);
}

// round 13
// speedup vs baseline: 1.4912x; 1.1655x over previous
#include <cuda_runtime.h>
#include <cuda_bf16.h>
#include <cuda_fp16.h>
#include <mma.h>
#include <math.h>
#include <cstdint>

using namespace nvcuda;

#define NHI 4096
#define NLO 262144
#define NT  (NHI + NLO)      /* 266240 = 260 * 1024 */
#define EHI 65536
#define ELO 524288
#define ET  (EHI + ELO)
#define DIM 128
#define NHEAD 4
#define HDIM 32
#define SCALE 0.17677669529663687f   /* 1/sqrt(32) */
#define NBLK 260             /* scan blocks */

// ---------------- scratch (device globals; no allocation allowed) ----------------
__device__ __half g_qh[(size_t)NT * DIM];    // q (fp16)
__device__ __half g_kvh[(size_t)NT * 256];   // k at +0, v at +128 (fp16)
__device__ __half g_hh[(size_t)NT * DIM];    // skip -> +agg+LN+relu in place (fp16)
__device__ int g_dcnt[NT];
__device__ int g_rowptr[NT + 1];
__device__ int g_cursor[NT];
__device__ int g_col[ET];
__device__ int g_bsum[NBLK];
__device__ int g_bex[NBLK];
// W^T fp16 image: [matrix 0..3][n 0..127][k 0..127]
__device__ __align__(16) __half g_wt[4 * 128 * 128];
// bias rows: [matrix][128]
__device__ __align__(16) float g_brow[4 * 128];

// ---------------- helpers ----------------
__device__ __forceinline__ float warp_sum(float v) {
    #pragma unroll
    for (int o = 16; o; o >>= 1) v += __shfl_xor_sync(0xffffffffu, v, o);
    return v;
}
__device__ __forceinline__ uint32_t smem_u32(const void* p) {
    uint32_t a;
    asm("{ .reg .u64 t; cvta.to.shared.u64 t, %1; cvt.u32.u64 %0, t; }"
        : "=r"(a) : "l"(p));
    return a;
}
__device__ __forceinline__ void cp_async16(uint32_t dst, const void* src) {
    asm volatile("cp.async.cg.shared.global [%0], [%1], 16;" :: "r"(dst), "l"(src));
}
__device__ __forceinline__ float4 hf8_to_f4(uint2 raw) {
    __half2 h0 = ((const __half2*)&raw)[0];
    __half2 h1 = ((const __half2*)&raw)[1];
    float2 f0 = __half22float2(h0);
    float2 f1 = __half22float2(h1);
    return make_float4(f0.x, f0.y, f1.x, f1.y);
}
__device__ __forceinline__ uint2 f4_to_hf8(float4 x) {
    __half2 p0 = __floats2half2_rn(x.x, x.y);
    __half2 p1 = __floats2half2_rn(x.z, x.w);
    return make_uint2(*(uint32_t*)&p0, *(uint32_t*)&p1);
}

// ---------------- K0a: prep weights -> W^T fp16 ----------------
__global__ void prep_w(const float* __restrict__ Wq, const float* __restrict__ Wk,
                       const float* __restrict__ Wv, const float* __restrict__ Ws)
{
    int idx = blockIdx.x * 256 + threadIdx.x;  // 0..65535
    int m = idx >> 14;       // matrix 0..3
    int n = (idx >> 7) & 127;
    int k = idx & 127;
    const float* W = (m == 0) ? Wq : (m == 1) ? Wk : (m == 2) ? Wv : Ws;
    g_wt[idx] = __float2half(W[k * 128 + n]);
}

// ---------------- K0b: prep bias rows ----------------
__global__ void prep_b(const float* __restrict__ bq, const float* __restrict__ bk,
                       const float* __restrict__ bv, const float* __restrict__ bs)
{
    int idx = blockIdx.x * 256 + threadIdx.x;  // 0..511
    int m = idx >> 7;
    int n = idx & 127;
    const float* B = (m == 0) ? bq : (m == 1) ? bk : (m == 2) ? bv : bs;
    g_brow[idx] = B[n];
}

// ---------------- K1: fused QKV+skip GEMM, fp16 HMMA, 32x64 warp tiles ----------------
// SMEM (half elems): A[64*136], B[128*136]   (B area doubles as f32 staging)
#define TILE_M 64
#define LDA 136
#define A_ELEMS (TILE_M * LDA)          /* 8704 */
#define SM_B    A_ELEMS
#define SM_TOT_ELEMS (SM_B + 128 * LDA) /* 26112 half elems */
#define SM_BYTES (SM_TOT_ELEMS * 2)     /* 52224 */
#define LDS_STAGE 132                   /* f32 staging stride (64*132*4 = 33792 <= 34816) */

__global__ void __launch_bounds__(128, 4)
gemm_hmma(const float* __restrict__ xh, const float* __restrict__ xl)
{
    extern __shared__ __half sm[];
    const uint32_t sbase = smem_u32(sm);
    const int t = threadIdx.x;       // 0..127
    const int wid = t >> 5;          // 0..3
    const int wm = wid & 1;          // warp row group: 32 rows
    const int wn = wid >> 1;         // warp col group: 64 cols

    // ---- load + convert A tile (64 rows x 128 k) to fp16 ----
    const int row0 = blockIdx.x * TILE_M;
    const float* X = (row0 < NHI) ? (xh + (size_t)row0 * DIM)
                                  : (xl + (size_t)(row0 - NHI) * DIM);
    #pragma unroll
    for (int j = 0; j < 16; j++) {
        int v = t + 128 * j;            // float4 index 0..2047
        int r = v >> 5;                 // row 0..63
        int k0 = (v & 31) * 4;          // k 0..124
        float4 x = ((const float4*)X)[v];
        *(uint2*)(sm + r * LDA + k0) = f4_to_hf8(x);
    }

    #pragma unroll
    for (int m = 0; m < 4; m++) {
        // load B[m] (single buffer; co-resident CTAs hide the wait)
        {
            const uint4* gw = (const uint4*)(g_wt + m * 128 * 128);
            uint32_t bb = sbase + SM_B * 2;
            #pragma unroll
            for (int j = 0; j < 16; j++) {
                int idx = t + 128 * j;      // 0..2047 (16B chunks)
                int n = idx >> 4;
                int c = idx & 15;
                uint32_t off = (uint32_t)(n * LDA + c * 8) * 2;
                cp_async16(bb + off, gw + idx);
            }
            asm volatile("cp.async.commit_group;");
            asm volatile("cp.async.wait_group 0;");
        }
        __syncthreads();   // B[m] ready; prior phase staging readers done

        const __half* B = sm + SM_B;

        wmma::fragment<wmma::accumulator, 16, 16, 16, float> acc[2][4];
        #pragma unroll
        for (int i = 0; i < 2; i++)
            #pragma unroll
            for (int j = 0; j < 4; j++)
                wmma::fill_fragment(acc[i][j], 0.0f);

        #pragma unroll
        for (int ks = 0; ks < 8; ks++) {
            wmma::fragment<wmma::matrix_a, 16, 16, 16, __half, wmma::row_major> af[2];
            #pragma unroll
            for (int i = 0; i < 2; i++)
                wmma::load_matrix_sync(af[i], sm + (wm * 32 + i * 16) * LDA + ks * 16, LDA);
            #pragma unroll
            for (int j = 0; j < 4; j++) {
                wmma::fragment<wmma::matrix_b, 16, 16, 16, __half, wmma::col_major> bf;
                wmma::load_matrix_sync(bf, B + (wn * 64 + j * 16) * LDA + ks * 16, LDA);
                wmma::mma_sync(acc[0][j], af[0], bf, acc[0][j]);
                wmma::mma_sync(acc[1][j], af[1], bf, acc[1][j]);
            }
        }

        // stage f32 in the B buffer (done being read), add bias, convert fp16, store
        __syncthreads();   // all warps done reading B[m]
        float* stage = (float*)(sm + SM_B);
        #pragma unroll
        for (int i = 0; i < 2; i++)
            #pragma unroll
            for (int j = 0; j < 4; j++)
                wmma::store_matrix_sync(
                    stage + (wm * 32 + i * 16) * LDS_STAGE + wn * 64 + j * 16,
                    acc[i][j], LDS_STAGE, wmma::mem_row_major);
        __syncthreads();

        __half* dst;
        int ldo;
        if (m == 0)      { dst = g_qh  + (size_t)row0 * DIM; ldo = 128; }
        else if (m == 1) { dst = g_kvh + (size_t)row0 * 256; ldo = 256; }
        else if (m == 2) { dst = g_kvh + (size_t)row0 * 256 + 128; ldo = 256; }
        else             { dst = g_hh  + (size_t)row0 * DIM; ldo = 128; }

        #pragma unroll
        for (int j = 0; j < 16; j++) {
            int v = t + 128 * j;        // 0..2047
            int r = v >> 5;
            int c = (v & 31) * 4;
            float4 x = *(const float4*)(stage + r * LDS_STAGE + c);
            float4 b4 = *(const float4*)&g_brow[m * 128 + c];
            x.x += b4.x; x.y += b4.y; x.z += b4.z; x.w += b4.w;
            *(uint2*)(dst + (size_t)r * ldo + c) = f4_to_hf8(x);
        }
        __syncthreads();   // staging free before next B load
    }
}

// ---------------- CSR build ----------------
__global__ void edge_hist(const int* __restrict__ eih, const int* __restrict__ eil)
{
    int e = blockIdx.x * 256 + threadIdx.x;
    if (e >= ET) return;
    int dst = (e < EHI) ? eih[EHI + e] : (eil[ELO + (e - EHI)] + NHI);
    atomicAdd(&g_dcnt[dst], 1);
}

__global__ void scan_local()
{
    __shared__ int sh[1024];
    const int t = threadIdx.x;
    const int i = blockIdx.x * 1024 + t;
    int v = g_dcnt[i];
    sh[t] = v;
    __syncthreads();
    #pragma unroll
    for (int off = 1; off < 1024; off <<= 1) {
        int u = (t >= off) ? sh[t - off] : 0;
        __syncthreads();
        sh[t] += u;
        __syncthreads();
    }
    g_rowptr[i] = sh[t] - v;            // local exclusive
    if (t == 1023) g_bsum[blockIdx.x] = sh[t];
}

__global__ void scan_bsum()
{
    __shared__ int sh[512];
    const int t = threadIdx.x;          // 512 threads
    int v = (t < NBLK) ? g_bsum[t] : 0;
    sh[t] = v;
    __syncthreads();
    #pragma unroll
    for (int off = 1; off < 512; off <<= 1) {
        int u = (t >= off) ? sh[t - off] : 0;
        __syncthreads();
        sh[t] += u;
        __syncthreads();
    }
    if (t < NBLK) g_bex[t] = sh[t] - v; // exclusive block base
    if (t == 511) g_rowptr[NT] = sh[511];
}

__global__ void scan_add()
{
    const int i = blockIdx.x * 1024 + threadIdx.x;
    int r = g_rowptr[i] + g_bex[blockIdx.x];
    g_rowptr[i] = r;
    g_cursor[i] = r;
}

__global__ void edge_scatter(const int* __restrict__ eih, const int* __restrict__ eil)
{
    int e = blockIdx.x * 256 + threadIdx.x;
    if (e >= ET) return;
    int src, dst;
    if (e < EHI) { src = eih[e];             dst = eih[EHI + e]; }
    else         { src = eil[e - EHI] + NHI; dst = eil[ELO + (e - EHI)] + NHI; }
    int pos = atomicAdd(&g_cursor[dst], 1);
    g_col[pos] = src;
}

// ---------------- K2: one-pass attention (online softmax) + fused LN/ReLU ----------------
// lane owns 4 contiguous columns [lane*4, lane*4+4); head = lane>>3.
__global__ void __launch_bounds__(256)
attn_ln(const float* __restrict__ lnw, const float* __restrict__ lnb)
{
    int node = blockIdx.x * 8 + threadIdx.y;
    int lane = threadIdx.x;
    int s = g_rowptr[node];
    int e1 = g_rowptr[node + 1];

    __half* hr = g_hh + (size_t)node * DIM;
    float4 val = hf8_to_f4(((uint2*)hr)[lane]);   // skip term

    if (s < e1) {
        float4 qv = hf8_to_f4(((const uint2*)(g_qh + (size_t)node * DIM))[lane]);

        float m = -INFINITY, d = 0.f;
        float4 acc = make_float4(0.f, 0.f, 0.f, 0.f);

        // 1-deep software pipeline on the kv gather (512B contiguous per edge)
        const uint2* kvp = (const uint2*)(g_kvh + (size_t)g_col[s] * 256);
        uint2 kraw = kvp[lane];
        uint2 vraw = kvp[lane + 32];
        for (int i = s; i < e1; i++) {
            float4 kc = hf8_to_f4(kraw);
            float4 vc = hf8_to_f4(vraw);
            if (i + 1 < e1) {
                const uint2* np = (const uint2*)(g_kvh + (size_t)g_col[i + 1] * 256);
                kraw = np[lane];
                vraw = np[lane + 32];
            }
            float p = qv.x * kc.x + qv.y * kc.y + qv.z * kc.z + qv.w * kc.w;
            p += __shfl_xor_sync(0xffffffffu, p, 4);
            p += __shfl_xor_sync(0xffffffffu, p, 2);
            p += __shfl_xor_sync(0xffffffffu, p, 1);
            float sc = p * SCALE;            // this lane's head score
            float mn = fmaxf(m, sc);
            float c = __expf(m - mn);        // 0 when m was -inf
            float w = __expf(sc - mn);
            d = d * c + w;
            acc.x = acc.x * c + w * vc.x;
            acc.y = acc.y * c + w * vc.y;
            acc.z = acc.z * c + w * vc.z;
            acc.w = acc.w * c + w * vc.w;
            m = mn;
        }
        float inv = 1.0f / d;
        val.x += acc.x * inv;
        val.y += acc.y * inv;
        val.z += acc.z * inv;
        val.w += acc.w * inv;
    }

    // fused LayerNorm + ReLU (warp holds the full 128-dim row)
    float sum = warp_sum(val.x + val.y + val.z + val.w);
    float sq = warp_sum(val.x * val.x + val.y * val.y + val.z * val.z + val.w * val.w);
    float mean = sum * (1.0f / 128.0f);
    float var = sq * (1.0f / 128.0f) - mean * mean;
    float rstd = rsqrtf(var + 1e-5f);
    float4 w4 = ((const float4*)lnw)[lane];
    float4 b4 = ((const float4*)lnb)[lane];
    float4 o;
    o.x = fmaxf((val.x - mean) * rstd * w4.x + b4.x, 0.0f);
    o.y = fmaxf((val.y - mean) * rstd * w4.y + b4.y, 0.0f);
    o.z = fmaxf((val.z - mean) * rstd * w4.z + b4.z, 0.0f);
    o.w = fmaxf((val.w - mean) * rstd * w4.w + b4.w, 0.0f);
    ((uint2*)hr)[lane] = f4_to_hf8(o);
}

// ---------------- K3: segmented pool + high-node gating (one warp per high node) ----------------
__device__ __forceinline__ int lower_bound_batch(const int* __restrict__ batch, int key)
{
    int lo = 0, hi = NLO;
    while (lo < hi) {
        int mid = (lo + hi) >> 1;
        if (batch[mid] < key) lo = mid + 1; else hi = mid;
    }
    return lo;
}

__global__ void __launch_bounds__(256)
pool_final_high(const int* __restrict__ batch, const float* __restrict__ wlh,
                float* __restrict__ out)
{
    int g = blockIdx.x * 8 + threadIdx.y;
    int lane = threadIdx.x;
    int lb = lower_bound_batch(batch, g);
    int ub = lower_bound_batch(batch, g + 1);

    float4 s = make_float4(0.f, 0.f, 0.f, 0.f);
    for (int j = lb; j < ub; j++) {
        float4 lr = hf8_to_f4(((const uint2*)(g_hh + (size_t)(NHI + j) * DIM))[lane]);
        s.x += lr.x; s.y += lr.y; s.z += lr.z; s.w += lr.w;
    }
    float inv = 1.0f / fmaxf((float)(ub - lb), 1.0f);
    float4 pv = make_float4(s.x * inv, s.y * inv, s.z * inv, s.w * inv);

    float4 hv = hf8_to_f4(((const uint2*)(g_hh + (size_t)g * DIM))[lane]);
    float4 w0 = ((const float4*)wlh)[lane];
    float4 w1 = ((const float4*)(wlh + DIM))[lane];
    float dot = hv.x * w0.x + hv.y * w0.y + hv.z * w0.z + hv.w * w0.w
              + pv.x * w1.x + pv.y * w1.y + pv.z * w1.z + pv.w * w1.w;
    dot = warp_sum(dot);
    float sgm = 1.0f / (1.0f + __expf(-dot));
    float4 o;
    o.x = sgm * hv.x + (1.0f - sgm) * pv.x;
    o.y = sgm * hv.y + (1.0f - sgm) * pv.y;
    o.z = sgm * hv.z + (1.0f - sgm) * pv.z;
    o.w = sgm * hv.w + (1.0f - sgm) * pv.w;
    ((float4*)(out + (size_t)g * DIM))[lane] = o;
}

// ---------------- K4: low-node gating epilogue ----------------
__global__ void final_low(const float* __restrict__ whl, const int* __restrict__ batch,
                          float* __restrict__ out)
{
    int j = blockIdx.x * 8 + threadIdx.y;
    int lane = threadIdx.x;
    int g = batch[j];
    float4 hb = hf8_to_f4(((const uint2*)(g_hh + (size_t)g * DIM))[lane]);
    float4 lv = hf8_to_f4(((const uint2*)(g_hh + (size_t)(NHI + j) * DIM))[lane]);
    float4 w0 = ((const float4*)whl)[lane];
    float4 w1 = ((const float4*)(whl + DIM))[lane];
    float d = hb.x * w0.x + hb.y * w0.y + hb.z * w0.z + hb.w * w0.w
            + lv.x * w1.x + lv.y * w1.y + lv.z * w1.z + lv.w * w1.w;
    d = warp_sum(d);
    float a = 1.0f / (1.0f + __expf(-d));
    float4 o;
    o.x = a * lv.x + (1.0f - a) * hb.x;
    o.y = a * lv.y + (1.0f - a) * hb.y;
    o.z = a * lv.z + (1.0f - a) * hb.z;
    o.w = a * lv.w + (1.0f - a) * hb.w;
    ((float4*)(out + (size_t)j * DIM))[lane] = o;
}

// ---------------- launch ----------------
extern "C" void kernel_launch(void* const* d_in, const int* in_sizes, int n_in,
                              void* d_out, int out_size)
{
    const float* high_emb = (const float*)d_in[0];
    const float* low_emb  = (const float*)d_in[1];
    const float* Wq = (const float*)d_in[2];  const float* bq = (const float*)d_in[3];
    const float* Wk = (const float*)d_in[4];  const float* bk = (const float*)d_in[5];
    const float* Wv = (const float*)d_in[6];  const float* bv = (const float*)d_in[7];
    const float* Ws = (const float*)d_in[8];  const float* bs = (const float*)d_in[9];
    const float* lnw = (const float*)d_in[10];
    const float* lnb = (const float*)d_in[11];
    const float* wlh = (const float*)d_in[12];
    const float* whl = (const float*)d_in[13];
    const int* eih   = (const int*)d_in[14];
    const int* eil   = (const int*)d_in[15];
    const int* batch = (const int*)d_in[16];
    float* out = (float*)d_out;

    void* pcnt;
    cudaGetSymbolAddress(&pcnt, g_dcnt);

    cudaFuncSetAttribute(gemm_hmma, cudaFuncAttributeMaxDynamicSharedMemorySize, SM_BYTES);

    // second stream + fork/join events (graph-capture-legal pattern)
    cudaStream_t s2;
    cudaStreamCreateWithFlags(&s2, cudaStreamNonBlocking);
    cudaEvent_t evFork, evCsr, evAttn, evPool;
    cudaEventCreateWithFlags(&evFork, cudaEventDisableTiming);
    cudaEventCreateWithFlags(&evCsr,  cudaEventDisableTiming);
    cudaEventCreateWithFlags(&evAttn, cudaEventDisableTiming);
    cudaEventCreateWithFlags(&evPool, cudaEventDisableTiming);

    cudaMemsetAsync(pcnt, 0, NT * sizeof(int), 0);
    cudaEventRecord(evFork, 0);
    cudaStreamWaitEvent(s2, evFork, 0);

    // stream 0: prep + GEMM (profiled slot); s2: CSR chain concurrently
    prep_w<<<256, 256>>>(Wq, Wk, Wv, Ws);
    prep_b<<<2, 256>>>(bq, bk, bv, bs);
    edge_hist<<<(ET + 255) / 256, 256, 0, s2>>>(eih, eil);
    gemm_hmma<<<NT / TILE_M, 128, SM_BYTES>>>(high_emb, low_emb);

    scan_local<<<NBLK, 1024, 0, s2>>>();
    scan_bsum<<<1, 512, 0, s2>>>();
    scan_add<<<NBLK, 1024, 0, s2>>>();
    edge_scatter<<<(ET + 255) / 256, 256, 0, s2>>>(eih, eil);
    cudaEventRecord(evCsr, s2);

    // join: attention needs both GEMM outputs and CSR
    cudaStreamWaitEvent(0, evCsr, 0);
    dim3 t32x8(32, 8);
    attn_ln<<<NT / 8, t32x8>>>(lnw, lnb);
    cudaEventRecord(evAttn, 0);

    // overlap the two epilogues
    cudaStreamWaitEvent(s2, evAttn, 0);
    pool_final_high<<<NHI / 8, t32x8, 0, s2>>>(batch, wlh, out);
    cudaEventRecord(evPool, s2);
    final_low<<<NLO / 8, t32x8>>>(whl, batch, out + (size_t)NHI * DIM);
    cudaStreamWaitEvent(0, evPool, 0);

    cudaEventDestroy(evFork);
    cudaEventDestroy(evCsr);
    cudaEventDestroy(evAttn);
    cudaEventDestroy(evPool);
    cudaStreamDestroy(s2);
}